// round 11
// baseline (speedup 1.0000x reference)
#include <cuda_runtime.h>
#include <cuda_fp16.h>
#include <math.h>
#include <stdint.h>

#define NN 4096
#define DD 512
#define NH 8
#define HD 64
#define NXD (NN * DD)
#define NW (DD * DD)

// Scratch (allocation-free rule: __device__ globals)
__device__ __half g_x[3 * NXD];             // query/key/value fp16 (contiguous)
__device__ __half g_w[4 * NW];              // Wq/Wk/Wv/Wo fp16
__device__ __half g_qkv[3 * NXD];           // Q(prescaled*log2e)/K/V projections fp16
__device__ __half g_ah[NXD];                // attention out fp16 row-major
__device__ __half g_sg_h[(size_t)NN * NN];  // sgconv_mat fp16
__device__ float  g_part[2 * NXD];          // sgconv split-K fp32 partials
__device__ __half g_gc_h[NXD];              // graph-conv out fp16

// ---------------------------------------------------------------------------
// helpers
// ---------------------------------------------------------------------------
__device__ __forceinline__ void mma_f16(float* c, const uint32_t* a, uint32_t b0, uint32_t b1) {
    asm volatile(
        "mma.sync.aligned.m16n8k16.row.col.f32.f16.f16.f32 "
        "{%0,%1,%2,%3}, {%4,%5,%6,%7}, {%8,%9}, {%0,%1,%2,%3};"
        : "+f"(c[0]), "+f"(c[1]), "+f"(c[2]), "+f"(c[3])
        : "r"(a[0]), "r"(a[1]), "r"(a[2]), "r"(a[3]), "r"(b0), "r"(b1));
}

__device__ __forceinline__ void ldsm_x4(uint32_t* r, const void* p) {
    uint32_t a = (uint32_t)__cvta_generic_to_shared(p);
    asm volatile("ldmatrix.sync.aligned.m8n8.x4.shared.b16 {%0,%1,%2,%3}, [%4];"
                 : "=r"(r[0]), "=r"(r[1]), "=r"(r[2]), "=r"(r[3]) : "r"(a));
}
__device__ __forceinline__ void ldsm_x4_t(uint32_t* r, const void* p) {
    uint32_t a = (uint32_t)__cvta_generic_to_shared(p);
    asm volatile("ldmatrix.sync.aligned.m8n8.x4.trans.shared.b16 {%0,%1,%2,%3}, [%4];"
                 : "=r"(r[0]), "=r"(r[1]), "=r"(r[2]), "=r"(r[3]) : "r"(a));
}

__device__ __forceinline__ void cpa16(void* dst, const void* src) {
    uint32_t d = (uint32_t)__cvta_generic_to_shared(dst);
    asm volatile("cp.async.cg.shared.global [%0], [%1], 16;" :: "r"(d), "l"(src));
}
#define CP_COMMIT() asm volatile("cp.async.commit_group;")
#define CP_WAIT(n)  asm volatile("cp.async.wait_group %0;" :: "n"(n))

__device__ __forceinline__ uint32_t h2exp2_u32(uint32_t x) {
    uint32_t r;
    asm("ex2.approx.f16x2 %0, %1;" : "=r"(r) : "r"(x));
    return r;
}

__device__ __forceinline__ void cvt8(const float* __restrict__ x, __half* __restrict__ y) {
    float4 v0 = *(const float4*)x;
    float4 v1 = *(const float4*)(x + 4);
    __half2 h[4];
    h[0] = __floats2half2_rn(v0.x, v0.y);
    h[1] = __floats2half2_rn(v0.z, v0.w);
    h[2] = __floats2half2_rn(v1.x, v1.y);
    h[3] = __floats2half2_rn(v1.z, v1.w);
    *(uint4*)y = *(uint4*)h;
}

// ---------------------------------------------------------------------------
// single convert launch for all 7 small tensors (q,k,v -> g_x; W* -> g_w).
// Region boundaries are multiples of 2048, so each block stays in one region.
// ---------------------------------------------------------------------------
__global__ __launch_bounds__(256)
void f2h_all(const float* __restrict__ q, const float* __restrict__ k,
             const float* __restrict__ v,
             const float* __restrict__ wq, const float* __restrict__ wk,
             const float* __restrict__ wv, const float* __restrict__ wo,
             __half* __restrict__ xh, __half* __restrict__ wh) {
    size_t e = (size_t)blockIdx.x * 2048 + threadIdx.x * 8;
    const float* src;
    __half* dst;
    if (e < (size_t)3 * NXD) {
        int r = (int)(e / NXD);
        size_t off = e - (size_t)r * NXD;
        src = (r == 0 ? q : r == 1 ? k : v) + off;
        dst = xh + e;
    } else {
        size_t ew = e - (size_t)3 * NXD;
        int r = (int)(ew / NW);
        size_t off = ew - (size_t)r * NW;
        src = (r == 0 ? wq : r == 1 ? wk : r == 2 ? wv : wo) + off;
        dst = wh + ew;
    }
    cvt8(src, dst);
}

// combine split-K partials: y = fp16(p0 + p1)
__global__ __launch_bounds__(256)
void combine2_kernel(const float* __restrict__ p, __half* __restrict__ y) {
    size_t i = ((size_t)blockIdx.x * 256 + threadIdx.x) * 4;
    float4 a = *(const float4*)&p[i];
    float4 b = *(const float4*)&p[i + NXD];
    __half2 h[2];
    h[0] = __floats2half2_rn(a.x + b.x, a.y + b.y);
    h[1] = __floats2half2_rn(a.z + b.z, a.w + b.w);
    *(uint2*)&y[i] = *(uint2*)h;
}

// ---------------------------------------------------------------------------
// fp16 tensor-core GEMM, fp32 accumulate. BM=128, BN=128, BK=64, 3-stage ring.
// 128 threads = 4 warps as 2(m) x 2(n); warp tile 64x64.
//   TRANSB=true : B is [N,K] row-major;  false: B is [K,N] row-major.
//   OMODE: 0 = fp32 row-major (+bias,alpha), 1 = fp16 row-major (+bias,alpha)
// grid.z batching: A += z*sAz, B += z*sBz, C += z*sCz,
//   bias = {bias0,bias1,bias2}[z], alpha = (z==0 ? alpha0 : 1).
// WITH_CVT: blockIdx.z == 3 CTAs instead convert cvt_n fp32->fp16 (overlap a
//   DRAM-bound convert with the compute-bound GEMM inside one launch).
// ---------------------------------------------------------------------------
#define ALD 72     // A smem stride (halfs)
#define BLD_T 72   // B stride, TRANSB (rows = n)
#define BLD_N 136  // B stride, non-trans (rows = k, 128 cols)

template <bool TRANSB, bool HAS_BIAS, int OMODE, bool WITH_CVT>
__global__ __launch_bounds__(128, 2)
void hgemm(const __half* __restrict__ A, int lda, long sAz,
           const __half* __restrict__ B, int ldb, long sBz,
           const float* __restrict__ bias0, const float* __restrict__ bias1,
           const float* __restrict__ bias2,
           void* __restrict__ Cv, int ldc, long sCz,
           int K, float alpha0,
           const float* __restrict__ cvt_src, __half* __restrict__ cvt_dst) {
    extern __shared__ __half hsm[];

    const int tid = threadIdx.x;

    if (WITH_CVT && blockIdx.z == 3) {
        // convert plane: 128 CTAs, each handles NN*NN/128 contiguous elems
        const int id = blockIdx.y * gridDim.x + blockIdx.x;      // 0..127
        const size_t share = (size_t)NN * NN / 128;              // 131072
        size_t base = (size_t)id * share;
#pragma unroll 4
        for (int it = 0; it < (int)(share / 1024); it++) {       // 128 iters
            size_t i = base + (size_t)it * 1024 + tid * 8;
            cvt8(cvt_src + i, cvt_dst + i);
        }
        return;
    }

    __half* As = hsm;                                  // [3][128][ALD]
    __half* Bs = hsm + 3 * 128 * ALD;                  // [3][...]
    const int BSTAGE = TRANSB ? 128 * BLD_T : 64 * BLD_N;

    const int warp = tid >> 5, lane = tid & 31;
    const int g = lane >> 2, t = lane & 3;
    const int wm = warp & 1, wn = warp >> 1;
    const int bm = blockIdx.y * 128, bn = blockIdx.x * 128;
    const int z = blockIdx.z;

    A += (long)z * sAz;
    B += (long)z * sBz;
    const float* bias = (z == 0) ? bias0 : (z == 1) ? bias1 : bias2;
    const float alpha = (z == 0) ? alpha0 : 1.0f;

    const int rA = lane & 15, cA = (lane >> 4) << 3;
    const int rB = (lane & 7) + ((lane >> 4) << 3), cB = lane & 8;

    float acc[4][8][4];
#pragma unroll
    for (int mi = 0; mi < 4; mi++)
#pragma unroll
        for (int ni = 0; ni < 8; ni++)
#pragma unroll
            for (int r = 0; r < 4; r++) acc[mi][ni][r] = 0.0f;

    auto loadStage = [&](int s, int k0) {
        __half* at = As + s * 128 * ALD;
        __half* bt = Bs + s * BSTAGE;
#pragma unroll
        for (int i = 0; i < 8; i++) {                 // A: 128x64 (1024 float4)
            int f = tid + i * 128;
            int row = f >> 3, cv = f & 7;
            cpa16(at + row * ALD + cv * 8, A + (size_t)(bm + row) * lda + k0 + cv * 8);
        }
        if (TRANSB) {
#pragma unroll
            for (int i = 0; i < 8; i++) {             // B: 128(n) x 64(k)
                int f = tid + i * 128;
                int row = f >> 3, cv = f & 7;
                cpa16(bt + row * BLD_T + cv * 8, B + (size_t)(bn + row) * ldb + k0 + cv * 8);
            }
        } else {
#pragma unroll
            for (int i = 0; i < 8; i++) {             // B: 64(k) x 128(n)
                int f = tid + i * 128;
                int row = f >> 4, cv = f & 15;
                cpa16(bt + row * BLD_N + cv * 8, B + (size_t)(k0 + row) * ldb + bn + cv * 8);
            }
        }
    };

    const int NT = K / 64;
    loadStage(0, 0);
    CP_COMMIT();
    if (NT > 1) { loadStage(1, 64); CP_COMMIT(); }

    for (int kt = 0; kt < NT; kt++) {
        if (kt + 1 < NT) CP_WAIT(1); else CP_WAIT(0);
        __syncthreads();
        if (kt + 2 < NT) { loadStage((kt + 2) % 3, (kt + 2) * 64); CP_COMMIT(); }

        const int s = kt % 3;
        __half* at = As + s * 128 * ALD;
        __half* bt = Bs + s * BSTAGE;

#pragma unroll
        for (int kk = 0; kk < 64; kk += 16) {
            uint32_t af[4][4];
#pragma unroll
            for (int mi = 0; mi < 4; mi++)
                ldsm_x4(af[mi], at + (wm * 64 + mi * 16 + rA) * ALD + kk + cA);
#pragma unroll
            for (int nip = 0; nip < 4; nip++) {
                uint32_t bf[4];
                if (TRANSB) {
                    ldsm_x4(bf, bt + (wn * 64 + nip * 16 + rB) * BLD_T + kk + cB);
#pragma unroll
                    for (int mi = 0; mi < 4; mi++) {
                        mma_f16(acc[mi][2 * nip], af[mi], bf[0], bf[1]);
                        mma_f16(acc[mi][2 * nip + 1], af[mi], bf[2], bf[3]);
                    }
                } else {
                    ldsm_x4_t(bf, bt + (kk + rB) * BLD_N + wn * 64 + nip * 16 + cB);
#pragma unroll
                    for (int mi = 0; mi < 4; mi++) {
                        mma_f16(acc[mi][2 * nip], af[mi], bf[0], bf[2]);
                        mma_f16(acc[mi][2 * nip + 1], af[mi], bf[1], bf[3]);
                    }
                }
            }
        }
        __syncthreads();
    }

#pragma unroll
    for (int mi = 0; mi < 4; mi++) {
#pragma unroll
        for (int ni = 0; ni < 8; ni++) {
            int row0 = bm + wm * 64 + mi * 16 + g;
            int col = bn + wn * 64 + ni * 8 + 2 * t;
            float b0 = 0.0f, b1 = 0.0f;
            if (HAS_BIAS) { b0 = bias[col]; b1 = bias[col + 1]; }
            float v00 = (acc[mi][ni][0] + b0) * alpha;
            float v01 = (acc[mi][ni][1] + b1) * alpha;
            float v10 = (acc[mi][ni][2] + b0) * alpha;
            float v11 = (acc[mi][ni][3] + b1) * alpha;
            if (OMODE == 0) {
                float* C = (float*)Cv + (long)z * sCz;
                *(float2*)&C[(size_t)row0 * ldc + col] = make_float2(v00, v01);
                *(float2*)&C[(size_t)(row0 + 8) * ldc + col] = make_float2(v10, v11);
            } else {
                __half* C = (__half*)Cv + (long)z * sCz;
                *(__half2*)&C[(size_t)row0 * ldc + col] = __floats2half2_rn(v00, v01);
                *(__half2*)&C[(size_t)(row0 + 8) * ldc + col] = __floats2half2_rn(v10, v11);
            }
        }
    }
}

// ---------------------------------------------------------------------------
// Fused flash attention, fp16 MMA, no max tracking (logits bounded after the
// scale). Q pre-scaled by log2(e)/sqrt(512): P = exp2(S') via ex2.approx.f16x2
// (approx bias cancels in the normalization — l is summed from the SAME
// rounded P used in PV).
// 128 threads = 4 warps, each owning 32 Q rows. 2 CTAs/SM.
// ---------------------------------------------------------------------------
#define BQ 128
#define BKV 64
#define LDH 72

__global__ __launch_bounds__(128, 2)
void flash_attn(const __half* __restrict__ Qh, const __half* __restrict__ Kh,
                const __half* __restrict__ V, __half* __restrict__ O) {
    extern __shared__ __half sm[];
    __half* Qs = sm;                        // [BQ][LDH]
    __half* Ks = Qs + BQ * LDH;             // [3][BKV][LDH]
    __half* Vs = Ks + 3 * BKV * LDH;        // [3][BKV][LDH]

    const int h = blockIdx.y;
    const int q0 = blockIdx.x * BQ;
    const int tid = threadIdx.x;
    const int warp = tid >> 5, lane = tid & 31;
    const int g = lane >> 2, t = lane & 3;

    const int rA = lane & 15, cA = (lane >> 4) << 3;
    const int rB = (lane & 7) + ((lane >> 4) << 3), cB = lane & 8;

#pragma unroll
    for (int i = 0; i < 8; i++) {
        int f = tid + i * 128;
        int row = f >> 3, cv = f & 7;
        cpa16(&Qs[row * LDH + cv * 8], Qh + (size_t)(q0 + row) * DD + h * HD + cv * 8);
    }

    auto loadKV = [&](int s, int kv0) {
#pragma unroll
        for (int i = 0; i < 4; i++) {
            int f = tid + i * 128;
            int row = f >> 3, cv = f & 7;
            cpa16(&Ks[(s * BKV + row) * LDH + cv * 8],
                  Kh + (size_t)(kv0 + row) * DD + h * HD + cv * 8);
        }
#pragma unroll
        for (int i = 0; i < 4; i++) {
            int f = tid + i * 128;
            int row = f >> 3, cv = f & 7;
            cpa16(&Vs[(s * BKV + row) * LDH + cv * 8],
                  V + (size_t)(kv0 + row) * DD + h * HD + cv * 8);
        }
    };

    loadKV(0, 0);
    CP_COMMIT();
    loadKV(1, BKV);
    CP_COMMIT();

    CP_WAIT(1);
    __syncthreads();

    uint32_t qa[4][2][4];
#pragma unroll
    for (int ks = 0; ks < 4; ks++)
#pragma unroll
        for (int mi = 0; mi < 2; mi++)
            ldsm_x4(qa[ks][mi], &Qs[(warp * 32 + mi * 16 + rA) * LDH + ks * 16 + cA]);

    float o[2][8][4];
#pragma unroll
    for (int mi = 0; mi < 2; mi++)
#pragma unroll
        for (int ni = 0; ni < 8; ni++)
#pragma unroll
            for (int r = 0; r < 4; r++) o[mi][ni][r] = 0.0f;
    float l[2][2] = {{0.0f, 0.0f}, {0.0f, 0.0f}};

    const int NT = NN / BKV;
    for (int it = 0; it < NT; it++) {
        if (it > 0) {
            if (it + 1 < NT) CP_WAIT(1); else CP_WAIT(0);
        }
        __syncthreads();
        if (it + 2 < NT) { loadKV((it + 2) % 3, (it + 2) * BKV); CP_COMMIT(); }

        const int s = it % 3;

        // ---- S' = (Q*log2e/sqrt(D)) K^T ----
        float sc[2][8][4];
#pragma unroll
        for (int mi = 0; mi < 2; mi++)
#pragma unroll
            for (int ni = 0; ni < 8; ni++)
#pragma unroll
                for (int r = 0; r < 4; r++) sc[mi][ni][r] = 0.0f;

#pragma unroll
        for (int ks = 0; ks < 4; ks++) {
#pragma unroll
            for (int nip = 0; nip < 4; nip++) {
                uint32_t b[4];
                ldsm_x4(b, &Ks[(s * BKV + nip * 16 + rB) * LDH + ks * 16 + cB]);
#pragma unroll
                for (int mi = 0; mi < 2; mi++) {
                    mma_f16(sc[mi][2 * nip], qa[ks][mi], b[0], b[1]);
                    mma_f16(sc[mi][2 * nip + 1], qa[ks][mi], b[2], b[3]);
                }
            }
        }

        // ---- P = exp2(S') in fp16x2; l summed from the same P ----
        uint32_t ph[2][8][2];
#pragma unroll
        for (int mi = 0; mi < 2; mi++) {
            float ps0 = 0.0f, ps1 = 0.0f;
#pragma unroll
            for (int ni = 0; ni < 8; ni++) {
                __half2 h0 = __floats2half2_rn(sc[mi][ni][0], sc[mi][ni][1]);
                __half2 h1 = __floats2half2_rn(sc[mi][ni][2], sc[mi][ni][3]);
                uint32_t e0 = h2exp2_u32(*(uint32_t*)&h0);
                uint32_t e1 = h2exp2_u32(*(uint32_t*)&h1);
                ph[mi][ni][0] = e0;
                ph[mi][ni][1] = e1;
                float2 f0 = __half22float2(*(__half2*)&e0);
                float2 f1 = __half22float2(*(__half2*)&e1);
                ps0 += f0.x + f0.y;
                ps1 += f1.x + f1.y;
            }
            l[mi][0] += ps0;
            l[mi][1] += ps1;
        }

        // ---- O += P V (V row-major -> trans ldsm; b reused across mi) ----
#pragma unroll
        for (int ks = 0; ks < 4; ks++) {
#pragma unroll
            for (int nip = 0; nip < 4; nip++) {
                uint32_t b[4];
                ldsm_x4_t(b, &Vs[(s * BKV + ks * 16 + rB) * LDH + nip * 16 + cB]);
#pragma unroll
                for (int mi = 0; mi < 2; mi++) {
                    uint32_t pa[4] = { ph[mi][2 * ks][0], ph[mi][2 * ks][1],
                                       ph[mi][2 * ks + 1][0], ph[mi][2 * ks + 1][1] };
                    mma_f16(o[mi][2 * nip], pa, b[0], b[2]);
                    mma_f16(o[mi][2 * nip + 1], pa, b[1], b[3]);
                }
            }
        }
        __syncthreads();
    }

#pragma unroll
    for (int mi = 0; mi < 2; mi++) {
        float l0 = l[mi][0], l1 = l[mi][1];
        l0 += __shfl_xor_sync(0xffffffffu, l0, 1);
        l0 += __shfl_xor_sync(0xffffffffu, l0, 2);
        l1 += __shfl_xor_sync(0xffffffffu, l1, 1);
        l1 += __shfl_xor_sync(0xffffffffu, l1, 2);
        float inv0 = 1.0f / l0, inv1 = 1.0f / l1;
        size_t base = (size_t)(q0 + warp * 32 + mi * 16 + g) * DD + h * HD;
#pragma unroll
        for (int ni = 0; ni < 8; ni++) {
            int col = ni * 8 + 2 * t;
            *(__half2*)&O[base + col] = __floats2half2_rn(o[mi][ni][0] * inv0, o[mi][ni][1] * inv0);
            *(__half2*)&O[base + 8 * DD + col] = __floats2half2_rn(o[mi][ni][2] * inv1, o[mi][ni][3] * inv1);
        }
    }
}

// ---------------------------------------------------------------------------
// kernel_launch: query,key,value, Wq,bq, Wk,bk, Wv,bv, Wo,bo, sgconv_mat
// ---------------------------------------------------------------------------
extern "C" void kernel_launch(void* const* d_in, const int* in_sizes, int n_in,
                              void* d_out, int out_size) {
    const float* query  = (const float*)d_in[0];
    const float* key    = (const float*)d_in[1];
    const float* value  = (const float*)d_in[2];
    const float* Wq     = (const float*)d_in[3];
    const float* bq     = (const float*)d_in[4];
    const float* Wk     = (const float*)d_in[5];
    const float* bk     = (const float*)d_in[6];
    const float* Wv     = (const float*)d_in[7];
    const float* bv     = (const float*)d_in[8];
    const float* Wo     = (const float*)d_in[9];
    const float* bo     = (const float*)d_in[10];
    const float* sgconv = (const float*)d_in[11];
    float* out = (float*)d_out;

    __half *xh, *wh, *qkv, *ah, *sgh, *gch;
    float *part;
    cudaGetSymbolAddress((void**)&xh, g_x);
    cudaGetSymbolAddress((void**)&wh, g_w);
    cudaGetSymbolAddress((void**)&qkv, g_qkv);
    cudaGetSymbolAddress((void**)&ah, g_ah);
    cudaGetSymbolAddress((void**)&sgh, g_sg_h);
    cudaGetSymbolAddress((void**)&part, g_part);
    cudaGetSymbolAddress((void**)&gch, g_gc_h);

    const int FLASH_SMEM = (BQ * LDH + 6 * BKV * LDH) * (int)sizeof(__half);
    cudaFuncSetAttribute(flash_attn, cudaFuncAttributeMaxDynamicSharedMemorySize, FLASH_SMEM);
    const int HG_SMEM_T = (3 * 128 * ALD + 3 * 128 * BLD_T) * (int)sizeof(__half);
    const int HG_SMEM_N = (3 * 128 * ALD + 3 * 64 * BLD_N) * (int)sizeof(__half);
    cudaFuncSetAttribute(hgemm<true, true, 1, true>,    cudaFuncAttributeMaxDynamicSharedMemorySize, HG_SMEM_T);
    cudaFuncSetAttribute(hgemm<true, true, 0, false>,   cudaFuncAttributeMaxDynamicSharedMemorySize, HG_SMEM_T);
    cudaFuncSetAttribute(hgemm<false, false, 0, false>, cudaFuncAttributeMaxDynamicSharedMemorySize, HG_SMEM_N);

    // 1/sqrt(512) * log2(e): flash uses exp2
    const float qscale = 0.04419417382415922f * 1.4426950408889634f;

    // one convert launch for q,k,v + all four weights
    const int CVT_BLOCKS = (3 * NXD + 4 * NW) / 2048;   // 3584
    f2h_all<<<CVT_BLOCKS, 256>>>(query, key, value, Wq, Wk, Wv, Wo, xh, wh);

    // QKV projections + sgconv convert fused in one launch:
    // z=0..2 -> GEMM planes (384 CTAs); z=3 -> 128 convert CTAs (DRAM-bound,
    // overlaps the GEMM's second wave).
    dim3 gqkv(DD / 128, NN / 128, 4);
    hgemm<true, true, 1, true><<<gqkv, 128, HG_SMEM_T>>>(
        xh, DD, NXD, wh, DD, NW, bq, bk, bv, qkv, DD, NXD, DD, qscale,
        sgconv, sgh);

    // fused flash attention -> fp16 row-major (grid 256 CTAs, 1 wave)
    dim3 agrid(NN / BQ, NH);
    flash_attn<<<agrid, 128, FLASH_SMEM>>>(qkv, qkv + NXD, qkv + 2 * NXD, ah);

    // graph conv split-K=2: grid (4, 32, 2) = 256 CTAs, fp32 partials
    dim3 gsg(DD / 128, NN / 128, 2);
    hgemm<false, false, 0, false><<<gsg, 128, HG_SMEM_N>>>(
        sgh, NN, 2048, ah, DD, (long)2048 * DD, nullptr, nullptr, nullptr,
        part, DD, NXD, 2048, 1.0f, nullptr, nullptr);
    combine2_kernel<<<NXD / 1024, 256>>>(part, gch);

    // output projection: gc @ Wo^T + bo -> fp32
    dim3 gop(DD / 128, NN / 128, 1);
    hgemm<true, true, 0, false><<<gop, 128, HG_SMEM_T>>>(
        gch, DD, 0, wh + 3 * (size_t)NW, DD, 0, bo, nullptr, nullptr,
        out, DD, 0, DD, 1.0f, nullptr, nullptr);
}

// round 12
// speedup vs baseline: 1.1261x; 1.1261x over previous
#include <cuda_runtime.h>
#include <cuda_fp16.h>
#include <math.h>
#include <stdint.h>

#define NN 4096
#define DD 512
#define NH 8
#define HD 64
#define NXD (NN * DD)
#define NW (DD * DD)

// Scratch (allocation-free rule: __device__ globals)
__device__ __half g_x[3 * NXD];             // query/key/value fp16 (contiguous)
__device__ __half g_w[4 * NW];              // Wq/Wk/Wv/Wo fp16
__device__ __half g_qkv[3 * NXD];           // Q(prescaled*log2e)/K/V projections fp16
__device__ __half g_ah[NXD];                // attention out fp16 row-major
__device__ __half g_sg_h[(size_t)NN * NN];  // sgconv_mat fp16
__device__ float  g_part[2 * NXD];          // sgconv split-K fp32 partials
__device__ __half g_gc_h[NXD];              // graph-conv out fp16

// ---------------------------------------------------------------------------
// helpers
// ---------------------------------------------------------------------------
__device__ __forceinline__ void mma_f16(float* c, const uint32_t* a, uint32_t b0, uint32_t b1) {
    asm volatile(
        "mma.sync.aligned.m16n8k16.row.col.f32.f16.f16.f32 "
        "{%0,%1,%2,%3}, {%4,%5,%6,%7}, {%8,%9}, {%0,%1,%2,%3};"
        : "+f"(c[0]), "+f"(c[1]), "+f"(c[2]), "+f"(c[3])
        : "r"(a[0]), "r"(a[1]), "r"(a[2]), "r"(a[3]), "r"(b0), "r"(b1));
}

__device__ __forceinline__ void ldsm_x4(uint32_t* r, const void* p) {
    uint32_t a = (uint32_t)__cvta_generic_to_shared(p);
    asm volatile("ldmatrix.sync.aligned.m8n8.x4.shared.b16 {%0,%1,%2,%3}, [%4];"
                 : "=r"(r[0]), "=r"(r[1]), "=r"(r[2]), "=r"(r[3]) : "r"(a));
}
__device__ __forceinline__ void ldsm_x4_t(uint32_t* r, const void* p) {
    uint32_t a = (uint32_t)__cvta_generic_to_shared(p);
    asm volatile("ldmatrix.sync.aligned.m8n8.x4.trans.shared.b16 {%0,%1,%2,%3}, [%4];"
                 : "=r"(r[0]), "=r"(r[1]), "=r"(r[2]), "=r"(r[3]) : "r"(a));
}

__device__ __forceinline__ void cpa16(void* dst, const void* src) {
    uint32_t d = (uint32_t)__cvta_generic_to_shared(dst);
    asm volatile("cp.async.cg.shared.global [%0], [%1], 16;" :: "r"(d), "l"(src));
}
#define CP_COMMIT() asm volatile("cp.async.commit_group;")
#define CP_WAIT(n)  asm volatile("cp.async.wait_group %0;" :: "n"(n))

__device__ __forceinline__ uint32_t h2exp2_u32(uint32_t x) {
    uint32_t r;
    asm("ex2.approx.f16x2 %0, %1;" : "=r"(r) : "r"(x));
    return r;
}

__device__ __forceinline__ void cvt8(const float* __restrict__ x, __half* __restrict__ y) {
    float4 v0 = *(const float4*)x;
    float4 v1 = *(const float4*)(x + 4);
    __half2 h[4];
    h[0] = __floats2half2_rn(v0.x, v0.y);
    h[1] = __floats2half2_rn(v0.z, v0.w);
    h[2] = __floats2half2_rn(v1.x, v1.y);
    h[3] = __floats2half2_rn(v1.z, v1.w);
    *(uint4*)y = *(uint4*)h;
}

// ---------------------------------------------------------------------------
// single convert launch for the 7 small tensors (q,k,v -> g_x; W* -> g_w).
// Region boundaries are multiples of 2048, so each block stays in one region.
// ---------------------------------------------------------------------------
__global__ __launch_bounds__(256)
void f2h_all(const float* __restrict__ q, const float* __restrict__ k,
             const float* __restrict__ v,
             const float* __restrict__ wq, const float* __restrict__ wk,
             const float* __restrict__ wv, const float* __restrict__ wo,
             __half* __restrict__ xh, __half* __restrict__ wh) {
    size_t e = (size_t)blockIdx.x * 2048 + threadIdx.x * 8;
    const float* src;
    __half* dst;
    if (e < (size_t)3 * NXD) {
        int r = (int)(e / NXD);
        size_t off = e - (size_t)r * NXD;
        src = (r == 0 ? q : r == 1 ? k : v) + off;
        dst = xh + e;
    } else {
        size_t ew = e - (size_t)3 * NXD;
        int r = (int)(ew / NW);
        size_t off = ew - (size_t)r * NW;
        src = (r == 0 ? wq : r == 1 ? wk : r == 2 ? wv : wo) + off;
        dst = wh + ew;
    }
    cvt8(src, dst);
}

// combine split-K partials: y = fp16(p0 + p1)
__global__ __launch_bounds__(256)
void combine2_kernel(const float* __restrict__ p, __half* __restrict__ y) {
    size_t i = ((size_t)blockIdx.x * 256 + threadIdx.x) * 4;
    float4 a = *(const float4*)&p[i];
    float4 b = *(const float4*)&p[i + NXD];
    __half2 h[2];
    h[0] = __floats2half2_rn(a.x + b.x, a.y + b.y);
    h[1] = __floats2half2_rn(a.z + b.z, a.w + b.w);
    *(uint2*)&y[i] = *(uint2*)h;
}

// ---------------------------------------------------------------------------
// fp16 tensor-core GEMM, fp32 accumulate. BM=128, BN=128, BK=64, 3-stage ring.
// 128 threads = 4 warps as 2(m) x 2(n); warp tile 64x64.  (R10 configuration)
// ---------------------------------------------------------------------------
#define ALD 72     // A smem stride (halfs)
#define BLD_T 72   // B stride, TRANSB (rows = n)
#define BLD_N 136  // B stride, non-trans (rows = k, 128 cols)

template <bool TRANSB, bool HAS_BIAS, int OMODE>
__global__ __launch_bounds__(128, 2)
void hgemm(const __half* __restrict__ A, int lda, long sAz,
           const __half* __restrict__ B, int ldb, long sBz,
           const float* __restrict__ bias0, const float* __restrict__ bias1,
           const float* __restrict__ bias2,
           void* __restrict__ Cv, int ldc, long sCz,
           int K, float alpha0) {
    extern __shared__ __half hsm[];
    __half* As = hsm;                                  // [3][128][ALD]
    __half* Bs = hsm + 3 * 128 * ALD;                  // [3][...]
    const int BSTAGE = TRANSB ? 128 * BLD_T : 64 * BLD_N;

    const int tid = threadIdx.x;
    const int warp = tid >> 5, lane = tid & 31;
    const int g = lane >> 2, t = lane & 3;
    const int wm = warp & 1, wn = warp >> 1;
    const int bm = blockIdx.y * 128, bn = blockIdx.x * 128;
    const int z = blockIdx.z;

    A += (long)z * sAz;
    B += (long)z * sBz;
    const float* bias = (z == 0) ? bias0 : (z == 1) ? bias1 : bias2;
    const float alpha = (z == 0) ? alpha0 : 1.0f;

    const int rA = lane & 15, cA = (lane >> 4) << 3;
    const int rB = (lane & 7) + ((lane >> 4) << 3), cB = lane & 8;

    float acc[4][8][4];
#pragma unroll
    for (int mi = 0; mi < 4; mi++)
#pragma unroll
        for (int ni = 0; ni < 8; ni++)
#pragma unroll
            for (int r = 0; r < 4; r++) acc[mi][ni][r] = 0.0f;

    auto loadStage = [&](int s, int k0) {
        __half* at = As + s * 128 * ALD;
        __half* bt = Bs + s * BSTAGE;
#pragma unroll
        for (int i = 0; i < 8; i++) {                 // A: 128x64 (1024 float4)
            int f = tid + i * 128;
            int row = f >> 3, cv = f & 7;
            cpa16(at + row * ALD + cv * 8, A + (size_t)(bm + row) * lda + k0 + cv * 8);
        }
        if (TRANSB) {
#pragma unroll
            for (int i = 0; i < 8; i++) {             // B: 128(n) x 64(k)
                int f = tid + i * 128;
                int row = f >> 3, cv = f & 7;
                cpa16(bt + row * BLD_T + cv * 8, B + (size_t)(bn + row) * ldb + k0 + cv * 8);
            }
        } else {
#pragma unroll
            for (int i = 0; i < 8; i++) {             // B: 64(k) x 128(n)
                int f = tid + i * 128;
                int row = f >> 4, cv = f & 15;
                cpa16(bt + row * BLD_N + cv * 8, B + (size_t)(k0 + row) * ldb + bn + cv * 8);
            }
        }
    };

    const int NT = K / 64;
    loadStage(0, 0);
    CP_COMMIT();
    if (NT > 1) { loadStage(1, 64); CP_COMMIT(); }

    for (int kt = 0; kt < NT; kt++) {
        if (kt + 1 < NT) CP_WAIT(1); else CP_WAIT(0);
        __syncthreads();
        if (kt + 2 < NT) { loadStage((kt + 2) % 3, (kt + 2) * 64); CP_COMMIT(); }

        const int s = kt % 3;
        __half* at = As + s * 128 * ALD;
        __half* bt = Bs + s * BSTAGE;

#pragma unroll
        for (int kk = 0; kk < 64; kk += 16) {
            uint32_t af[4][4];
#pragma unroll
            for (int mi = 0; mi < 4; mi++)
                ldsm_x4(af[mi], at + (wm * 64 + mi * 16 + rA) * ALD + kk + cA);
#pragma unroll
            for (int nip = 0; nip < 4; nip++) {
                uint32_t bf[4];
                if (TRANSB) {
                    ldsm_x4(bf, bt + (wn * 64 + nip * 16 + rB) * BLD_T + kk + cB);
#pragma unroll
                    for (int mi = 0; mi < 4; mi++) {
                        mma_f16(acc[mi][2 * nip], af[mi], bf[0], bf[1]);
                        mma_f16(acc[mi][2 * nip + 1], af[mi], bf[2], bf[3]);
                    }
                } else {
                    ldsm_x4_t(bf, bt + (kk + rB) * BLD_N + wn * 64 + nip * 16 + cB);
#pragma unroll
                    for (int mi = 0; mi < 4; mi++) {
                        mma_f16(acc[mi][2 * nip], af[mi], bf[0], bf[2]);
                        mma_f16(acc[mi][2 * nip + 1], af[mi], bf[1], bf[3]);
                    }
                }
            }
        }
        __syncthreads();
    }

#pragma unroll
    for (int mi = 0; mi < 4; mi++) {
#pragma unroll
        for (int ni = 0; ni < 8; ni++) {
            int row0 = bm + wm * 64 + mi * 16 + g;
            int col = bn + wn * 64 + ni * 8 + 2 * t;
            float b0 = 0.0f, b1 = 0.0f;
            if (HAS_BIAS) { b0 = bias[col]; b1 = bias[col + 1]; }
            float v00 = (acc[mi][ni][0] + b0) * alpha;
            float v01 = (acc[mi][ni][1] + b1) * alpha;
            float v10 = (acc[mi][ni][2] + b0) * alpha;
            float v11 = (acc[mi][ni][3] + b1) * alpha;
            if (OMODE == 0) {
                float* C = (float*)Cv + (long)z * sCz;
                *(float2*)&C[(size_t)row0 * ldc + col] = make_float2(v00, v01);
                *(float2*)&C[(size_t)(row0 + 8) * ldc + col] = make_float2(v10, v11);
            } else {
                __half* C = (__half*)Cv + (long)z * sCz;
                *(__half2*)&C[(size_t)row0 * ldc + col] = __floats2half2_rn(v00, v01);
                *(__half2*)&C[(size_t)(row0 + 8) * ldc + col] = __floats2half2_rn(v10, v11);
            }
        }
    }
}

// ---------------------------------------------------------------------------
// Fused flash attention (R10 core) + concurrent sgconv convert plane.
// grid (32, NH+1): y<NH = attention (256 CTAs = 2/SM on 128 SMs),
// y==NH = 32 convert CTAs that fill the remaining 40 resident slots and
// stream the 96MB sgconv fp32->fp16 concurrently (flash DRAM util is ~1%).
// 256+32 = 288 <= 296 resident slots -> one wave, no displacement.
// ---------------------------------------------------------------------------
#define BQ 128
#define BKV 64
#define LDH 72

__global__ __launch_bounds__(128, 2)
void flash_attn(const __half* __restrict__ Qh, const __half* __restrict__ Kh,
                const __half* __restrict__ V, __half* __restrict__ O,
                const float* __restrict__ cvt_src, __half* __restrict__ cvt_dst) {
    // ---- convert plane ----
    if (blockIdx.y == NH) {
        const int tid = threadIdx.x;
        const size_t share = (size_t)NN * NN / 32;     // 524288 elems per CTA
        size_t base = (size_t)blockIdx.x * share;
#pragma unroll 8
        for (int it = 0; it < (int)(share / 1024); it++) {   // 512 iters
            size_t i = base + (size_t)it * 1024 + tid * 8;
            cvt8(cvt_src + i, cvt_dst + i);
        }
        return;
    }

    extern __shared__ __half sm[];
    __half* Qs = sm;                        // [BQ][LDH]
    __half* Ks = Qs + BQ * LDH;             // [3][BKV][LDH]
    __half* Vs = Ks + 3 * BKV * LDH;        // [3][BKV][LDH]

    const int h = blockIdx.y;
    const int q0 = blockIdx.x * BQ;
    const int tid = threadIdx.x;
    const int warp = tid >> 5, lane = tid & 31;
    const int g = lane >> 2, t = lane & 3;

    const int rA = lane & 15, cA = (lane >> 4) << 3;
    const int rB = (lane & 7) + ((lane >> 4) << 3), cB = lane & 8;

#pragma unroll
    for (int i = 0; i < 8; i++) {
        int f = tid + i * 128;
        int row = f >> 3, cv = f & 7;
        cpa16(&Qs[row * LDH + cv * 8], Qh + (size_t)(q0 + row) * DD + h * HD + cv * 8);
    }

    auto loadKV = [&](int s, int kv0) {
#pragma unroll
        for (int i = 0; i < 4; i++) {
            int f = tid + i * 128;
            int row = f >> 3, cv = f & 7;
            cpa16(&Ks[(s * BKV + row) * LDH + cv * 8],
                  Kh + (size_t)(kv0 + row) * DD + h * HD + cv * 8);
        }
#pragma unroll
        for (int i = 0; i < 4; i++) {
            int f = tid + i * 128;
            int row = f >> 3, cv = f & 7;
            cpa16(&Vs[(s * BKV + row) * LDH + cv * 8],
                  V + (size_t)(kv0 + row) * DD + h * HD + cv * 8);
        }
    };

    loadKV(0, 0);
    CP_COMMIT();
    loadKV(1, BKV);
    CP_COMMIT();

    CP_WAIT(1);
    __syncthreads();

    uint32_t qa[4][2][4];
#pragma unroll
    for (int ks = 0; ks < 4; ks++)
#pragma unroll
        for (int mi = 0; mi < 2; mi++)
            ldsm_x4(qa[ks][mi], &Qs[(warp * 32 + mi * 16 + rA) * LDH + ks * 16 + cA]);

    float o[2][8][4];
#pragma unroll
    for (int mi = 0; mi < 2; mi++)
#pragma unroll
        for (int ni = 0; ni < 8; ni++)
#pragma unroll
            for (int r = 0; r < 4; r++) o[mi][ni][r] = 0.0f;
    float l[2][2] = {{0.0f, 0.0f}, {0.0f, 0.0f}};

    const int NT = NN / BKV;
    for (int it = 0; it < NT; it++) {
        if (it > 0) {
            if (it + 1 < NT) CP_WAIT(1); else CP_WAIT(0);
        }
        __syncthreads();
        if (it + 2 < NT) { loadKV((it + 2) % 3, (it + 2) * BKV); CP_COMMIT(); }

        const int s = it % 3;

        // ---- S' = (Q*log2e/sqrt(D)) K^T ----
        float sc[2][8][4];
#pragma unroll
        for (int mi = 0; mi < 2; mi++)
#pragma unroll
            for (int ni = 0; ni < 8; ni++)
#pragma unroll
                for (int r = 0; r < 4; r++) sc[mi][ni][r] = 0.0f;

#pragma unroll
        for (int ks = 0; ks < 4; ks++) {
#pragma unroll
            for (int nip = 0; nip < 4; nip++) {
                uint32_t b[4];
                ldsm_x4(b, &Ks[(s * BKV + nip * 16 + rB) * LDH + ks * 16 + cB]);
#pragma unroll
                for (int mi = 0; mi < 2; mi++) {
                    mma_f16(sc[mi][2 * nip], qa[ks][mi], b[0], b[1]);
                    mma_f16(sc[mi][2 * nip + 1], qa[ks][mi], b[2], b[3]);
                }
            }
        }

        // ---- P = exp2(S') in fp16x2; l summed from the same P ----
        uint32_t ph[2][8][2];
#pragma unroll
        for (int mi = 0; mi < 2; mi++) {
            float ps0 = 0.0f, ps1 = 0.0f;
#pragma unroll
            for (int ni = 0; ni < 8; ni++) {
                __half2 h0 = __floats2half2_rn(sc[mi][ni][0], sc[mi][ni][1]);
                __half2 h1 = __floats2half2_rn(sc[mi][ni][2], sc[mi][ni][3]);
                uint32_t e0 = h2exp2_u32(*(uint32_t*)&h0);
                uint32_t e1 = h2exp2_u32(*(uint32_t*)&h1);
                ph[mi][ni][0] = e0;
                ph[mi][ni][1] = e1;
                float2 f0 = __half22float2(*(__half2*)&e0);
                float2 f1 = __half22float2(*(__half2*)&e1);
                ps0 += f0.x + f0.y;
                ps1 += f1.x + f1.y;
            }
            l[mi][0] += ps0;
            l[mi][1] += ps1;
        }

        // ---- O += P V (V row-major -> trans ldsm; b reused across mi) ----
#pragma unroll
        for (int ks = 0; ks < 4; ks++) {
#pragma unroll
            for (int nip = 0; nip < 4; nip++) {
                uint32_t b[4];
                ldsm_x4_t(b, &Vs[(s * BKV + ks * 16 + rB) * LDH + nip * 16 + cB]);
#pragma unroll
                for (int mi = 0; mi < 2; mi++) {
                    uint32_t pa[4] = { ph[mi][2 * ks][0], ph[mi][2 * ks][1],
                                       ph[mi][2 * ks + 1][0], ph[mi][2 * ks + 1][1] };
                    mma_f16(o[mi][2 * nip], pa, b[0], b[2]);
                    mma_f16(o[mi][2 * nip + 1], pa, b[1], b[3]);
                }
            }
        }
        __syncthreads();
    }

#pragma unroll
    for (int mi = 0; mi < 2; mi++) {
        float l0 = l[mi][0], l1 = l[mi][1];
        l0 += __shfl_xor_sync(0xffffffffu, l0, 1);
        l0 += __shfl_xor_sync(0xffffffffu, l0, 2);
        l1 += __shfl_xor_sync(0xffffffffu, l1, 1);
        l1 += __shfl_xor_sync(0xffffffffu, l1, 2);
        float inv0 = 1.0f / l0, inv1 = 1.0f / l1;
        size_t base = (size_t)(q0 + warp * 32 + mi * 16 + g) * DD + h * HD;
#pragma unroll
        for (int ni = 0; ni < 8; ni++) {
            int col = ni * 8 + 2 * t;
            *(__half2*)&O[base + col] = __floats2half2_rn(o[mi][ni][0] * inv0, o[mi][ni][1] * inv0);
            *(__half2*)&O[base + 8 * DD + col] = __floats2half2_rn(o[mi][ni][2] * inv1, o[mi][ni][3] * inv1);
        }
    }
}

// ---------------------------------------------------------------------------
// kernel_launch: query,key,value, Wq,bq, Wk,bk, Wv,bv, Wo,bo, sgconv_mat
// ---------------------------------------------------------------------------
extern "C" void kernel_launch(void* const* d_in, const int* in_sizes, int n_in,
                              void* d_out, int out_size) {
    const float* query  = (const float*)d_in[0];
    const float* key    = (const float*)d_in[1];
    const float* value  = (const float*)d_in[2];
    const float* Wq     = (const float*)d_in[3];
    const float* bq     = (const float*)d_in[4];
    const float* Wk     = (const float*)d_in[5];
    const float* bk     = (const float*)d_in[6];
    const float* Wv     = (const float*)d_in[7];
    const float* bv     = (const float*)d_in[8];
    const float* Wo     = (const float*)d_in[9];
    const float* bo     = (const float*)d_in[10];
    const float* sgconv = (const float*)d_in[11];
    float* out = (float*)d_out;

    __half *xh, *wh, *qkv, *ah, *sgh, *gch;
    float *part;
    cudaGetSymbolAddress((void**)&xh, g_x);
    cudaGetSymbolAddress((void**)&wh, g_w);
    cudaGetSymbolAddress((void**)&qkv, g_qkv);
    cudaGetSymbolAddress((void**)&ah, g_ah);
    cudaGetSymbolAddress((void**)&sgh, g_sg_h);
    cudaGetSymbolAddress((void**)&part, g_part);
    cudaGetSymbolAddress((void**)&gch, g_gc_h);

    const int FLASH_SMEM = (BQ * LDH + 6 * BKV * LDH) * (int)sizeof(__half);
    cudaFuncSetAttribute(flash_attn, cudaFuncAttributeMaxDynamicSharedMemorySize, FLASH_SMEM);
    const int HG_SMEM_T = (3 * 128 * ALD + 3 * 128 * BLD_T) * (int)sizeof(__half);
    const int HG_SMEM_N = (3 * 128 * ALD + 3 * 64 * BLD_N) * (int)sizeof(__half);
    cudaFuncSetAttribute(hgemm<true, true, 1>,   cudaFuncAttributeMaxDynamicSharedMemorySize, HG_SMEM_T);
    cudaFuncSetAttribute(hgemm<true, true, 0>,   cudaFuncAttributeMaxDynamicSharedMemorySize, HG_SMEM_T);
    cudaFuncSetAttribute(hgemm<false, false, 0>, cudaFuncAttributeMaxDynamicSharedMemorySize, HG_SMEM_N);

    // 1/sqrt(512) * log2(e): flash uses exp2
    const float qscale = 0.04419417382415922f * 1.4426950408889634f;

    // one convert launch for q,k,v + all four weights
    const int CVT_BLOCKS = (3 * NXD + 4 * NW) / 2048;   // 3584
    f2h_all<<<CVT_BLOCKS, 256>>>(query, key, value, Wq, Wk, Wv, Wo, xh, wh);

    // QKV projections, one batched launch: grid (4, 32, 3) = 384 CTAs
    dim3 gqkv(DD / 128, NN / 128, 3);
    hgemm<true, true, 1><<<gqkv, 128, HG_SMEM_T>>>(
        xh, DD, NXD, wh, DD, NW, bq, bk, bv, qkv, DD, NXD, DD, qscale);

    // flash attention (256 CTAs) + concurrent sgconv convert (32 CTAs):
    // grid (32, 9) = 288 CTAs = one resident wave at 2 CTAs/SM.
    dim3 agrid(NN / BQ, NH + 1);
    flash_attn<<<agrid, 128, FLASH_SMEM>>>(qkv, qkv + NXD, qkv + 2 * NXD, ah,
                                           sgconv, sgh);

    // graph conv split-K=2: grid (4, 32, 2) = 256 CTAs, fp32 partials
    dim3 gsg(DD / 128, NN / 128, 2);
    hgemm<false, false, 0><<<gsg, 128, HG_SMEM_N>>>(
        sgh, NN, 2048, ah, DD, (long)2048 * DD, nullptr, nullptr, nullptr,
        part, DD, NXD, 2048, 1.0f);
    combine2_kernel<<<NXD / 1024, 256>>>(part, gch);

    // output projection: gc @ Wo^T + bo -> fp32
    dim3 gop(DD / 128, NN / 128, 1);
    hgemm<true, true, 0><<<gop, 128, HG_SMEM_T>>>(
        gch, DD, 0, wh + 3 * (size_t)NW, DD, 0, bo, nullptr, nullptr,
        out, DD, 0, DD, 1.0f);
}

// round 13
// speedup vs baseline: 1.1331x; 1.0062x over previous
#include <cuda_runtime.h>
#include <cuda_fp16.h>
#include <math.h>
#include <stdint.h>

#define NN 4096
#define DD 512
#define NH 8
#define HD 64
#define NXD (NN * DD)
#define NW (DD * DD)

// Scratch (allocation-free rule: __device__ globals)
__device__ __half g_x[3 * NXD];             // query/key/value fp16 (contiguous)
__device__ __half g_w[4 * NW];              // Wq/Wk/Wv/Wo fp16
__device__ __half g_qkv[3 * NXD];           // Q(prescaled*log2e)/K/V projections fp16
__device__ __half g_ah[NXD];                // attention out fp16 row-major
__device__ __half g_sg_h[(size_t)NN * NN];  // sgconv_mat fp16
__device__ float  g_part[2 * NXD];          // sgconv split-K fp32 partials
__device__ __half g_gc_h[NXD];              // graph-conv out fp16

// ---------------------------------------------------------------------------
// helpers
// ---------------------------------------------------------------------------
__device__ __forceinline__ void mma_f16(float* c, const uint32_t* a, uint32_t b0, uint32_t b1) {
    asm volatile(
        "mma.sync.aligned.m16n8k16.row.col.f32.f16.f16.f32 "
        "{%0,%1,%2,%3}, {%4,%5,%6,%7}, {%8,%9}, {%0,%1,%2,%3};"
        : "+f"(c[0]), "+f"(c[1]), "+f"(c[2]), "+f"(c[3])
        : "r"(a[0]), "r"(a[1]), "r"(a[2]), "r"(a[3]), "r"(b0), "r"(b1));
}

__device__ __forceinline__ void ldsm_x4(uint32_t* r, const void* p) {
    uint32_t a = (uint32_t)__cvta_generic_to_shared(p);
    asm volatile("ldmatrix.sync.aligned.m8n8.x4.shared.b16 {%0,%1,%2,%3}, [%4];"
                 : "=r"(r[0]), "=r"(r[1]), "=r"(r[2]), "=r"(r[3]) : "r"(a));
}
__device__ __forceinline__ void ldsm_x4_t(uint32_t* r, const void* p) {
    uint32_t a = (uint32_t)__cvta_generic_to_shared(p);
    asm volatile("ldmatrix.sync.aligned.m8n8.x4.trans.shared.b16 {%0,%1,%2,%3}, [%4];"
                 : "=r"(r[0]), "=r"(r[1]), "=r"(r[2]), "=r"(r[3]) : "r"(a));
}

__device__ __forceinline__ void cpa16(void* dst, const void* src) {
    uint32_t d = (uint32_t)__cvta_generic_to_shared(dst);
    asm volatile("cp.async.cg.shared.global [%0], [%1], 16;" :: "r"(d), "l"(src));
}
#define CP_COMMIT() asm volatile("cp.async.commit_group;")
#define CP_WAIT(n)  asm volatile("cp.async.wait_group %0;" :: "n"(n))

__device__ __forceinline__ uint32_t h2exp2_u32(uint32_t x) {
    uint32_t r;
    asm("ex2.approx.f16x2 %0, %1;" : "=r"(r) : "r"(x));
    return r;
}

__device__ __forceinline__ void cvt8(const float* __restrict__ x, __half* __restrict__ y) {
    float4 v0 = *(const float4*)x;
    float4 v1 = *(const float4*)(x + 4);
    __half2 h[4];
    h[0] = __floats2half2_rn(v0.x, v0.y);
    h[1] = __floats2half2_rn(v0.z, v0.w);
    h[2] = __floats2half2_rn(v1.x, v1.y);
    h[3] = __floats2half2_rn(v1.z, v1.w);
    *(uint4*)y = *(uint4*)h;
}

// ---------------------------------------------------------------------------
// single convert launch for the 7 small tensors (q,k,v -> g_x; W* -> g_w).
// ---------------------------------------------------------------------------
__global__ __launch_bounds__(256)
void f2h_all(const float* __restrict__ q, const float* __restrict__ k,
             const float* __restrict__ v,
             const float* __restrict__ wq, const float* __restrict__ wk,
             const float* __restrict__ wv, const float* __restrict__ wo,
             __half* __restrict__ xh, __half* __restrict__ wh) {
    size_t e = (size_t)blockIdx.x * 2048 + threadIdx.x * 8;
    const float* src;
    __half* dst;
    if (e < (size_t)3 * NXD) {
        int r = (int)(e / NXD);
        size_t off = e - (size_t)r * NXD;
        src = (r == 0 ? q : r == 1 ? k : v) + off;
        dst = xh + e;
    } else {
        size_t ew = e - (size_t)3 * NXD;
        int r = (int)(ew / NW);
        size_t off = ew - (size_t)r * NW;
        src = (r == 0 ? wq : r == 1 ? wk : r == 2 ? wv : wo) + off;
        dst = wh + ew;
    }
    cvt8(src, dst);
}

// combine split-K partials: y = fp16(p0 + p1)
__global__ __launch_bounds__(256)
void combine2_kernel(const float* __restrict__ p, __half* __restrict__ y) {
    size_t i = ((size_t)blockIdx.x * 256 + threadIdx.x) * 4;
    float4 a = *(const float4*)&p[i];
    float4 b = *(const float4*)&p[i + NXD];
    __half2 h[2];
    h[0] = __floats2half2_rn(a.x + b.x, a.y + b.y);
    h[1] = __floats2half2_rn(a.z + b.z, a.w + b.w);
    *(uint2*)&y[i] = *(uint2*)h;
}

// ---------------------------------------------------------------------------
// fp16 tensor-core GEMM, fp32 accumulate. BM=128, BN=128, BK=64, 3-stage ring,
// SINGLE barrier per stage (prefetch issued after the barrier, so a warp can
// only overwrite a stage all warps have finished: sync at top of kt+1 implies
// compute of kt done everywhere; prefetch target (kt+3)%3 == kt%3).
// 128 threads = 4 warps as 2(m) x 2(n); warp tile 64x64.
// ---------------------------------------------------------------------------
#define ALD 72     // A smem stride (halfs)
#define BLD_T 72   // B stride, TRANSB (rows = n)
#define BLD_N 136  // B stride, non-trans (rows = k, 128 cols)

template <bool TRANSB, bool HAS_BIAS, int OMODE>
__global__ __launch_bounds__(128, 2)
void hgemm(const __half* __restrict__ A, int lda, long sAz,
           const __half* __restrict__ B, int ldb, long sBz,
           const float* __restrict__ bias0, const float* __restrict__ bias1,
           const float* __restrict__ bias2,
           void* __restrict__ Cv, int ldc, long sCz,
           int K, float alpha0) {
    extern __shared__ __half hsm[];
    __half* As = hsm;                                  // [3][128][ALD]
    __half* Bs = hsm + 3 * 128 * ALD;                  // [3][...]
    const int BSTAGE = TRANSB ? 128 * BLD_T : 64 * BLD_N;

    const int tid = threadIdx.x;
    const int warp = tid >> 5, lane = tid & 31;
    const int g = lane >> 2, t = lane & 3;
    const int wm = warp & 1, wn = warp >> 1;
    const int bm = blockIdx.y * 128, bn = blockIdx.x * 128;
    const int z = blockIdx.z;

    A += (long)z * sAz;
    B += (long)z * sBz;
    const float* bias = (z == 0) ? bias0 : (z == 1) ? bias1 : bias2;
    const float alpha = (z == 0) ? alpha0 : 1.0f;

    const int rA = lane & 15, cA = (lane >> 4) << 3;
    const int rB = (lane & 7) + ((lane >> 4) << 3), cB = lane & 8;

    float acc[4][8][4];
#pragma unroll
    for (int mi = 0; mi < 4; mi++)
#pragma unroll
        for (int ni = 0; ni < 8; ni++)
#pragma unroll
            for (int r = 0; r < 4; r++) acc[mi][ni][r] = 0.0f;

    auto loadStage = [&](int s, int k0) {
        __half* at = As + s * 128 * ALD;
        __half* bt = Bs + s * BSTAGE;
#pragma unroll
        for (int i = 0; i < 8; i++) {                 // A: 128x64 (1024 float4)
            int f = tid + i * 128;
            int row = f >> 3, cv = f & 7;
            cpa16(at + row * ALD + cv * 8, A + (size_t)(bm + row) * lda + k0 + cv * 8);
        }
        if (TRANSB) {
#pragma unroll
            for (int i = 0; i < 8; i++) {             // B: 128(n) x 64(k)
                int f = tid + i * 128;
                int row = f >> 3, cv = f & 7;
                cpa16(bt + row * BLD_T + cv * 8, B + (size_t)(bn + row) * ldb + k0 + cv * 8);
            }
        } else {
#pragma unroll
            for (int i = 0; i < 8; i++) {             // B: 64(k) x 128(n)
                int f = tid + i * 128;
                int row = f >> 4, cv = f & 15;
                cpa16(bt + row * BLD_N + cv * 8, B + (size_t)(k0 + row) * ldb + bn + cv * 8);
            }
        }
    };

    const int NT = K / 64;
    loadStage(0, 0);
    CP_COMMIT();
    if (NT > 1) { loadStage(1, 64); CP_COMMIT(); }

    for (int kt = 0; kt < NT; kt++) {
        if (kt + 1 < NT) CP_WAIT(1); else CP_WAIT(0);
        __syncthreads();                      // single barrier per stage
        if (kt + 2 < NT) { loadStage((kt + 2) % 3, (kt + 2) * 64); CP_COMMIT(); }

        const int s = kt % 3;
        __half* at = As + s * 128 * ALD;
        __half* bt = Bs + s * BSTAGE;

#pragma unroll
        for (int kk = 0; kk < 64; kk += 16) {
            uint32_t af[4][4];
#pragma unroll
            for (int mi = 0; mi < 4; mi++)
                ldsm_x4(af[mi], at + (wm * 64 + mi * 16 + rA) * ALD + kk + cA);
#pragma unroll
            for (int nip = 0; nip < 4; nip++) {
                uint32_t bf[4];
                if (TRANSB) {
                    ldsm_x4(bf, bt + (wn * 64 + nip * 16 + rB) * BLD_T + kk + cB);
#pragma unroll
                    for (int mi = 0; mi < 4; mi++) {
                        mma_f16(acc[mi][2 * nip], af[mi], bf[0], bf[1]);
                        mma_f16(acc[mi][2 * nip + 1], af[mi], bf[2], bf[3]);
                    }
                } else {
                    ldsm_x4_t(bf, bt + (kk + rB) * BLD_N + wn * 64 + nip * 16 + cB);
#pragma unroll
                    for (int mi = 0; mi < 4; mi++) {
                        mma_f16(acc[mi][2 * nip], af[mi], bf[0], bf[2]);
                        mma_f16(acc[mi][2 * nip + 1], af[mi], bf[1], bf[3]);
                    }
                }
            }
        }
        // no trailing barrier: next iteration's top barrier provides the guard
    }

#pragma unroll
    for (int mi = 0; mi < 4; mi++) {
#pragma unroll
        for (int ni = 0; ni < 8; ni++) {
            int row0 = bm + wm * 64 + mi * 16 + g;
            int col = bn + wn * 64 + ni * 8 + 2 * t;
            float b0 = 0.0f, b1 = 0.0f;
            if (HAS_BIAS) { b0 = bias[col]; b1 = bias[col + 1]; }
            float v00 = (acc[mi][ni][0] + b0) * alpha;
            float v01 = (acc[mi][ni][1] + b1) * alpha;
            float v10 = (acc[mi][ni][2] + b0) * alpha;
            float v11 = (acc[mi][ni][3] + b1) * alpha;
            if (OMODE == 0) {
                float* C = (float*)Cv + (long)z * sCz;
                *(float2*)&C[(size_t)row0 * ldc + col] = make_float2(v00, v01);
                *(float2*)&C[(size_t)(row0 + 8) * ldc + col] = make_float2(v10, v11);
            } else {
                __half* C = (__half*)Cv + (long)z * sCz;
                *(__half2*)&C[(size_t)row0 * ldc + col] = __floats2half2_rn(v00, v01);
                *(__half2*)&C[(size_t)(row0 + 8) * ldc + col] = __floats2half2_rn(v10, v11);
            }
        }
    }
}

// ---------------------------------------------------------------------------
// Fused flash attention (single barrier per KV tile) + concurrent sgconv
// convert plane. grid (32, NH+1): y<NH attention (256 CTAs), y==NH 32 convert
// CTAs filling the spare resident slots (256+32=288 <= 296, one wave).
// ---------------------------------------------------------------------------
#define BQ 128
#define BKV 64
#define LDH 72

__global__ __launch_bounds__(128, 2)
void flash_attn(const __half* __restrict__ Qh, const __half* __restrict__ Kh,
                const __half* __restrict__ V, __half* __restrict__ O,
                const float* __restrict__ cvt_src, __half* __restrict__ cvt_dst) {
    // ---- convert plane ----
    if (blockIdx.y == NH) {
        const int tid = threadIdx.x;
        const size_t share = (size_t)NN * NN / 32;     // 524288 elems per CTA
        size_t base = (size_t)blockIdx.x * share;
#pragma unroll 8
        for (int it = 0; it < (int)(share / 1024); it++) {
            size_t i = base + (size_t)it * 1024 + tid * 8;
            cvt8(cvt_src + i, cvt_dst + i);
        }
        return;
    }

    extern __shared__ __half sm[];
    __half* Qs = sm;                        // [BQ][LDH]
    __half* Ks = Qs + BQ * LDH;             // [3][BKV][LDH]
    __half* Vs = Ks + 3 * BKV * LDH;        // [3][BKV][LDH]

    const int h = blockIdx.y;
    const int q0 = blockIdx.x * BQ;
    const int tid = threadIdx.x;
    const int warp = tid >> 5, lane = tid & 31;
    const int g = lane >> 2, t = lane & 3;

    const int rA = lane & 15, cA = (lane >> 4) << 3;
    const int rB = (lane & 7) + ((lane >> 4) << 3), cB = lane & 8;

#pragma unroll
    for (int i = 0; i < 8; i++) {
        int f = tid + i * 128;
        int row = f >> 3, cv = f & 7;
        cpa16(&Qs[row * LDH + cv * 8], Qh + (size_t)(q0 + row) * DD + h * HD + cv * 8);
    }

    auto loadKV = [&](int s, int kv0) {
#pragma unroll
        for (int i = 0; i < 4; i++) {
            int f = tid + i * 128;
            int row = f >> 3, cv = f & 7;
            cpa16(&Ks[(s * BKV + row) * LDH + cv * 8],
                  Kh + (size_t)(kv0 + row) * DD + h * HD + cv * 8);
        }
#pragma unroll
        for (int i = 0; i < 4; i++) {
            int f = tid + i * 128;
            int row = f >> 3, cv = f & 7;
            cpa16(&Vs[(s * BKV + row) * LDH + cv * 8],
                  V + (size_t)(kv0 + row) * DD + h * HD + cv * 8);
        }
    };

    loadKV(0, 0);
    CP_COMMIT();
    loadKV(1, BKV);
    CP_COMMIT();

    CP_WAIT(1);
    __syncthreads();

    uint32_t qa[4][2][4];
#pragma unroll
    for (int ks = 0; ks < 4; ks++)
#pragma unroll
        for (int mi = 0; mi < 2; mi++)
            ldsm_x4(qa[ks][mi], &Qs[(warp * 32 + mi * 16 + rA) * LDH + ks * 16 + cA]);

    float o[2][8][4];
#pragma unroll
    for (int mi = 0; mi < 2; mi++)
#pragma unroll
        for (int ni = 0; ni < 8; ni++)
#pragma unroll
            for (int r = 0; r < 4; r++) o[mi][ni][r] = 0.0f;
    float l[2][2] = {{0.0f, 0.0f}, {0.0f, 0.0f}};

    const int NT = NN / BKV;
    for (int it = 0; it < NT; it++) {
        if (it > 0) {
            if (it + 1 < NT) CP_WAIT(1); else CP_WAIT(0);
            __syncthreads();                // single barrier per tile
        }
        if (it + 2 < NT) { loadKV((it + 2) % 3, (it + 2) * BKV); CP_COMMIT(); }

        const int s = it % 3;

        // ---- S' = (Q*log2e/sqrt(D)) K^T ----
        float sc[2][8][4];
#pragma unroll
        for (int mi = 0; mi < 2; mi++)
#pragma unroll
            for (int ni = 0; ni < 8; ni++)
#pragma unroll
                for (int r = 0; r < 4; r++) sc[mi][ni][r] = 0.0f;

#pragma unroll
        for (int ks = 0; ks < 4; ks++) {
#pragma unroll
            for (int nip = 0; nip < 4; nip++) {
                uint32_t b[4];
                ldsm_x4(b, &Ks[(s * BKV + nip * 16 + rB) * LDH + ks * 16 + cB]);
#pragma unroll
                for (int mi = 0; mi < 2; mi++) {
                    mma_f16(sc[mi][2 * nip], qa[ks][mi], b[0], b[1]);
                    mma_f16(sc[mi][2 * nip + 1], qa[ks][mi], b[2], b[3]);
                }
            }
        }

        // ---- P = exp2(S') in fp16x2; l summed from the same P ----
        uint32_t ph[2][8][2];
#pragma unroll
        for (int mi = 0; mi < 2; mi++) {
            float ps0 = 0.0f, ps1 = 0.0f;
#pragma unroll
            for (int ni = 0; ni < 8; ni++) {
                __half2 h0 = __floats2half2_rn(sc[mi][ni][0], sc[mi][ni][1]);
                __half2 h1 = __floats2half2_rn(sc[mi][ni][2], sc[mi][ni][3]);
                uint32_t e0 = h2exp2_u32(*(uint32_t*)&h0);
                uint32_t e1 = h2exp2_u32(*(uint32_t*)&h1);
                ph[mi][ni][0] = e0;
                ph[mi][ni][1] = e1;
                float2 f0 = __half22float2(*(__half2*)&e0);
                float2 f1 = __half22float2(*(__half2*)&e1);
                ps0 += f0.x + f0.y;
                ps1 += f1.x + f1.y;
            }
            l[mi][0] += ps0;
            l[mi][1] += ps1;
        }

        // ---- O += P V (V row-major -> trans ldsm; b reused across mi) ----
#pragma unroll
        for (int ks = 0; ks < 4; ks++) {
#pragma unroll
            for (int nip = 0; nip < 4; nip++) {
                uint32_t b[4];
                ldsm_x4_t(b, &Vs[(s * BKV + ks * 16 + rB) * LDH + nip * 16 + cB]);
#pragma unroll
                for (int mi = 0; mi < 2; mi++) {
                    uint32_t pa[4] = { ph[mi][2 * ks][0], ph[mi][2 * ks][1],
                                       ph[mi][2 * ks + 1][0], ph[mi][2 * ks + 1][1] };
                    mma_f16(o[mi][2 * nip], pa, b[0], b[2]);
                    mma_f16(o[mi][2 * nip + 1], pa, b[1], b[3]);
                }
            }
        }
        // no trailing barrier
    }

#pragma unroll
    for (int mi = 0; mi < 2; mi++) {
        float l0 = l[mi][0], l1 = l[mi][1];
        l0 += __shfl_xor_sync(0xffffffffu, l0, 1);
        l0 += __shfl_xor_sync(0xffffffffu, l0, 2);
        l1 += __shfl_xor_sync(0xffffffffu, l1, 1);
        l1 += __shfl_xor_sync(0xffffffffu, l1, 2);
        float inv0 = 1.0f / l0, inv1 = 1.0f / l1;
        size_t base = (size_t)(q0 + warp * 32 + mi * 16 + g) * DD + h * HD;
#pragma unroll
        for (int ni = 0; ni < 8; ni++) {
            int col = ni * 8 + 2 * t;
            *(__half2*)&O[base + col] = __floats2half2_rn(o[mi][ni][0] * inv0, o[mi][ni][1] * inv0);
            *(__half2*)&O[base + 8 * DD + col] = __floats2half2_rn(o[mi][ni][2] * inv1, o[mi][ni][3] * inv1);
        }
    }
}

// ---------------------------------------------------------------------------
// kernel_launch: query,key,value, Wq,bq, Wk,bk, Wv,bv, Wo,bo, sgconv_mat
// ---------------------------------------------------------------------------
extern "C" void kernel_launch(void* const* d_in, const int* in_sizes, int n_in,
                              void* d_out, int out_size) {
    const float* query  = (const float*)d_in[0];
    const float* key    = (const float*)d_in[1];
    const float* value  = (const float*)d_in[2];
    const float* Wq     = (const float*)d_in[3];
    const float* bq     = (const float*)d_in[4];
    const float* Wk     = (const float*)d_in[5];
    const float* bk     = (const float*)d_in[6];
    const float* Wv     = (const float*)d_in[7];
    const float* bv     = (const float*)d_in[8];
    const float* Wo     = (const float*)d_in[9];
    const float* bo     = (const float*)d_in[10];
    const float* sgconv = (const float*)d_in[11];
    float* out = (float*)d_out;

    __half *xh, *wh, *qkv, *ah, *sgh, *gch;
    float *part;
    cudaGetSymbolAddress((void**)&xh, g_x);
    cudaGetSymbolAddress((void**)&wh, g_w);
    cudaGetSymbolAddress((void**)&qkv, g_qkv);
    cudaGetSymbolAddress((void**)&ah, g_ah);
    cudaGetSymbolAddress((void**)&sgh, g_sg_h);
    cudaGetSymbolAddress((void**)&part, g_part);
    cudaGetSymbolAddress((void**)&gch, g_gc_h);

    const int FLASH_SMEM = (BQ * LDH + 6 * BKV * LDH) * (int)sizeof(__half);
    cudaFuncSetAttribute(flash_attn, cudaFuncAttributeMaxDynamicSharedMemorySize, FLASH_SMEM);
    const int HG_SMEM_T = (3 * 128 * ALD + 3 * 128 * BLD_T) * (int)sizeof(__half);
    const int HG_SMEM_N = (3 * 128 * ALD + 3 * 64 * BLD_N) * (int)sizeof(__half);
    cudaFuncSetAttribute(hgemm<true, true, 1>,   cudaFuncAttributeMaxDynamicSharedMemorySize, HG_SMEM_T);
    cudaFuncSetAttribute(hgemm<true, true, 0>,   cudaFuncAttributeMaxDynamicSharedMemorySize, HG_SMEM_T);
    cudaFuncSetAttribute(hgemm<false, false, 0>, cudaFuncAttributeMaxDynamicSharedMemorySize, HG_SMEM_N);

    // 1/sqrt(512) * log2(e): flash uses exp2
    const float qscale = 0.04419417382415922f * 1.4426950408889634f;

    // one convert launch for q,k,v + all four weights
    const int CVT_BLOCKS = (3 * NXD + 4 * NW) / 2048;   // 3584
    f2h_all<<<CVT_BLOCKS, 256>>>(query, key, value, Wq, Wk, Wv, Wo, xh, wh);

    // QKV projections, one batched launch: grid (4, 32, 3) = 384 CTAs
    dim3 gqkv(DD / 128, NN / 128, 3);
    hgemm<true, true, 1><<<gqkv, 128, HG_SMEM_T>>>(
        xh, DD, NXD, wh, DD, NW, bq, bk, bv, qkv, DD, NXD, DD, qscale);

    // flash attention (256 CTAs) + concurrent sgconv convert (32 CTAs)
    dim3 agrid(NN / BQ, NH + 1);
    flash_attn<<<agrid, 128, FLASH_SMEM>>>(qkv, qkv + NXD, qkv + 2 * NXD, ah,
                                           sgconv, sgh);

    // graph conv split-K=2: grid (4, 32, 2) = 256 CTAs, fp32 partials
    dim3 gsg(DD / 128, NN / 128, 2);
    hgemm<false, false, 0><<<gsg, 128, HG_SMEM_N>>>(
        sgh, NN, 2048, ah, DD, (long)2048 * DD, nullptr, nullptr, nullptr,
        part, DD, NXD, 2048, 1.0f);
    combine2_kernel<<<NXD / 1024, 256>>>(part, gch);

    // output projection: gc @ Wo^T + bo -> fp32
    dim3 gop(DD / 128, NN / 128, 1);
    hgemm<true, true, 0><<<gop, 128, HG_SMEM_T>>>(
        gch, DD, 0, wh + 3 * (size_t)NW, DD, 0, bo, nullptr, nullptr,
        out, DD, 0, DD, 1.0f);
}